// round 16
// baseline (speedup 1.0000x reference)
#include <cuda_runtime.h>
#include <cuda_bf16.h>
#include <math.h>
#include <stdint.h>

#define MTOT   16384      // B*N = 4*4096
#define DMODEL 1024
#define NHEADS 16
#define HDIM   64
#define BATCH  4
#define SEQ    4096
#define BH     (BATCH*NHEADS)   // 64
#define NCHUNK 8

// ---------------- scratch (device globals: allocation-free) ----------------
__device__ float g_Y[(size_t)MTOT*DMODEL];
__device__ __nv_bfloat16 g_Ah[(size_t)MTOT*DMODEL];
__device__ __nv_bfloat16 g_Al[(size_t)MTOT*DMODEL];
__device__ __nv_bfloat16 g_Qh[(size_t)MTOT*DMODEL];
__device__ __nv_bfloat16 g_Ql[(size_t)MTOT*DMODEL];
__device__ __nv_bfloat16 g_Kh[(size_t)MTOT*DMODEL];
__device__ __nv_bfloat16 g_Kl[(size_t)MTOT*DMODEL];
__device__ __nv_bfloat16 g_Vh[(size_t)MTOT*DMODEL];
__device__ __nv_bfloat16 g_Vl[(size_t)MTOT*DMODEL];
__device__ __nv_bfloat16 g_WTh[4ULL*DMODEL*DMODEL];   // [w][n][k]
__device__ __nv_bfloat16 g_WTl[4ULL*DMODEL*DMODEL];
__device__ float g_KV[BH*HDIM*HDIM];                  // [bh][d][e] fp32 accum
__device__ __nv_bfloat16 g_KVTh[BH*HDIM*HDIM];        // [bh][e][d]
__device__ __nv_bfloat16 g_KVTl[BH*HDIM*HDIM];
__device__ float g_Ksum[BH*HDIM];

__device__ __forceinline__ void split2(float x, __nv_bfloat16& h, __nv_bfloat16& l) {
    h = __float2bfloat16_rn(x);
    l = __float2bfloat16_rn(x - __bfloat162float(h));
}
__device__ __forceinline__ uint32_t pack2(__nv_bfloat16 a, __nv_bfloat16 b) {
    __nv_bfloat162 t{a, b};
    return *(uint32_t*)&t;
}

// ---------------- PTX helpers ----------------------------------------------
__device__ __forceinline__ uint32_t s2u(const void* p) {
    uint32_t a;
    asm("{ .reg .u64 t; cvta.to.shared.u64 t, %1; cvt.u32.u64 %0, t; }"
        : "=r"(a) : "l"(p));
    return a;
}
__device__ __forceinline__ void cp16(uint32_t dst, const void* src) {
    asm volatile("cp.async.cg.shared.global [%0], [%1], 16;\n" :: "r"(dst), "l"(src));
}
__device__ __forceinline__ void cp_commit() { asm volatile("cp.async.commit_group;\n"); }
template<int N> __device__ __forceinline__ void cp_wait() {
    asm volatile("cp.async.wait_group %0;\n" :: "n"(N));
}
__device__ __forceinline__ void ldm_x4(uint32_t r[4], uint32_t addr) {
    asm volatile("ldmatrix.sync.aligned.m8n8.x4.shared.b16 {%0,%1,%2,%3}, [%4];"
        : "=r"(r[0]), "=r"(r[1]), "=r"(r[2]), "=r"(r[3]) : "r"(addr));
}
__device__ __forceinline__ void ldm_x4t(uint32_t r[4], uint32_t addr) {
    asm volatile("ldmatrix.sync.aligned.m8n8.x4.trans.shared.b16 {%0,%1,%2,%3}, [%4];"
        : "=r"(r[0]), "=r"(r[1]), "=r"(r[2]), "=r"(r[3]) : "r"(addr));
}
__device__ __forceinline__ void mma_bf16(float c[4],
    uint32_t a0, uint32_t a1, uint32_t a2, uint32_t a3, uint32_t b0, uint32_t b1) {
    asm volatile(
        "mma.sync.aligned.m16n8k16.row.col.f32.bf16.bf16.f32 "
        "{%0,%1,%2,%3}, {%4,%5,%6,%7}, {%8,%9}, {%0,%1,%2,%3};"
        : "+f"(c[0]), "+f"(c[1]), "+f"(c[2]), "+f"(c[3])
        : "r"(a0), "r"(a1), "r"(a2), "r"(a3), "r"(b0), "r"(b1));
}
__device__ __forceinline__ uint32_t sw64(uint32_t off) {
    return off ^ ((off >> 3) & 0x30);
}

// ---------------- prep: weight split+transpose | x split | zero KV ---------
// blocks [0,4096): split_tr (b>>10 selects weight); [4096,6144): split_rm;
// [6144,7168): zero KV/Ksum.
__global__ __launch_bounds__(256) void prep_k(
    const float* __restrict__ x,
    const float* __restrict__ W0, const float* __restrict__ W1,
    const float* __restrict__ W2, const float* __restrict__ W3,
    __nv_bfloat16* __restrict__ Ah, __nv_bfloat16* __restrict__ Al,
    __nv_bfloat16* __restrict__ Th, __nv_bfloat16* __restrict__ Tl,
    float* __restrict__ KV, float* __restrict__ Ksum)
{
    __shared__ float tile[32][33];
    int b = blockIdx.x, tid = threadIdx.x;
    if (b < 4096) {
        int wz = b >> 10;
        int n0 = (b & 31) * 32;
        int k0 = ((b >> 5) & 31) * 32;
        int tx = tid & 31, ty = tid >> 5;   // (32, 8)
        const float* W = (wz == 0) ? W0 : (wz == 1) ? W1 : (wz == 2) ? W2 : W3;
        const size_t WSZ = (size_t)DMODEL*DMODEL;
        #pragma unroll
        for (int i = 0; i < 32; i += 8)
            tile[ty+i][tx] = W[(size_t)(k0+ty+i)*DMODEL + n0 + tx];
        __syncthreads();
        #pragma unroll
        for (int i = 0; i < 32; i += 8) {
            float v = tile[tx][ty+i];
            __nv_bfloat16 h, l; split2(v, h, l);
            size_t o = wz*WSZ + (size_t)(n0+ty+i)*DMODEL + k0 + tx;
            Th[o] = h; Tl[o] = l;
        }
    } else if (b < 6144) {
        const int n4 = MTOT*DMODEL/4;
        for (int i = (b-4096)*256 + tid; i < n4; i += 2048*256) {
            float4 v = ((const float4*)x)[i];
            __nv_bfloat16 h0,h1,h2,h3,l0,l1,l2,l3;
            split2(v.x,h0,l0); split2(v.y,h1,l1); split2(v.z,h2,l2); split2(v.w,h3,l3);
            __nv_bfloat162* Hp = (__nv_bfloat162*)Ah;
            __nv_bfloat162* Lp = (__nv_bfloat162*)Al;
            Hp[i*2+0] = __nv_bfloat162{h0,h1}; Hp[i*2+1] = __nv_bfloat162{h2,h3};
            Lp[i*2+0] = __nv_bfloat162{l0,l1}; Lp[i*2+1] = __nv_bfloat162{l2,l3};
        }
    } else {
        int i = (b-6144)*256 + tid;
        if (i < BH*HDIM*HDIM) KV[i] = 0.f;
        if (i < BH*HDIM)      Ksum[i] = 0.f;
    }
}

// ---------------- bf16-split dense GEMM core (3-stage, pipelined) ----------
#define BM 128
#define BN 128
#define BK 32
#define STG 8192
#define NSTAGE 3
#define BUFSZ (NSTAGE*STG)
#define GSMEM (4*BUFSZ)              // 98304

struct GemmCtx {
    uint32_t bAh, bAl, bBh, bBl;
    uint32_t aoffA, aoffB;
    uint32_t d0sw, d1sw;
    const __nv_bfloat16 *AhR, *AlR, *BhR, *BlR;
    size_t g0, g1;
};

__device__ __forceinline__ void gemm_ctx_init(GemmCtx& cx, uint32_t sb,
    int row0, int col0, int tid,
    const __nv_bfloat16* Ahg, const __nv_bfloat16* Alg,
    const __nv_bfloat16* BTh, const __nv_bfloat16* BTl)
{
    cx.bAh = sb + 0*BUFSZ;  cx.bAl = sb + 1*BUFSZ;
    cx.bBh = sb + 2*BUFSZ;  cx.bBl = sb + 3*BUFSZ;
    int w = tid >> 5, lane = tid & 31;
    int wm = (w & 1) * 64, wn = (w >> 1) * 32;
    uint32_t linA = (uint32_t)((wm + (lane & 15)) * 64 + (lane >> 4) * 16);
    cx.aoffA = sw64(linA);
    uint32_t linB = (uint32_t)((wn + (lane & 7) + ((lane >> 4) << 3)) * 64 +
                               ((lane >> 3) & 1) * 16);
    cx.aoffB = sw64(linB);
    int r0 = tid >> 2,          c0 = tid & 3;
    int r1 = (tid + 256) >> 2,  c1 = (tid + 256) & 3;
    cx.d0sw = sw64((uint32_t)(r0*64 + c0*16));
    cx.d1sw = sw64((uint32_t)(r1*64 + c1*16));
    cx.g0 = (size_t)r0*DMODEL + c0*8;
    cx.g1 = (size_t)r1*DMODEL + c1*8;
    cx.AhR = Ahg + (size_t)row0 * DMODEL;
    cx.AlR = Alg + (size_t)row0 * DMODEL;
    cx.BhR = BTh + (size_t)col0 * DMODEL;
    cx.BlR = BTl + (size_t)col0 * DMODEL;
}

__device__ __forceinline__ void gemm_issue(GemmCtx& cx, int st, int k0) {
    uint32_t s = (uint32_t)st * STG;
    cp16(cx.bAh + s + cx.d0sw, cx.AhR + cx.g0 + k0);
    cp16(cx.bAh + s + cx.d1sw, cx.AhR + cx.g1 + k0);
    cp16(cx.bAl + s + cx.d0sw, cx.AlR + cx.g0 + k0);
    cp16(cx.bAl + s + cx.d1sw, cx.AlR + cx.g1 + k0);
    cp16(cx.bBh + s + cx.d0sw, cx.BhR + cx.g0 + k0);
    cp16(cx.bBh + s + cx.d1sw, cx.BhR + cx.g1 + k0);
    cp16(cx.bBl + s + cx.d0sw, cx.BlR + cx.g0 + k0);
    cp16(cx.bBl + s + cx.d1sw, cx.BlR + cx.g1 + k0);
    cp_commit();
}

__device__ __forceinline__ void gemm_load_frag(GemmCtx& cx, uint32_t sA, uint32_t kso,
    uint32_t af[4][4], uint32_t bh[8], uint32_t bl[8])
{
    uint32_t aA = cx.aoffA ^ kso;
    uint32_t aB = cx.aoffB ^ kso;
    #pragma unroll
    for (int p = 0; p < 2; p++) {
        ldm_x4(&bh[p*4], cx.bBh + sA + aB + p*1024);
        ldm_x4(&bl[p*4], cx.bBl + sA + aB + p*1024);
    }
    #pragma unroll
    for (int mt = 0; mt < 4; mt++)
        ldm_x4(af[mt], cx.bAh + sA + aA + mt*1024);
}

__device__ __forceinline__ void gemm_mma_group(GemmCtx& cx, uint32_t sA, uint32_t kso,
    uint32_t af[4][4], uint32_t bh[8], uint32_t bl[8], float acc[4][4][4])
{
    #pragma unroll
    for (int mt = 0; mt < 4; mt++)
        #pragma unroll
        for (int nt = 0; nt < 4; nt++) {
            mma_bf16(acc[mt][nt], af[mt][0],af[mt][1],af[mt][2],af[mt][3],
                     bh[nt*2], bh[nt*2+1]);
            mma_bf16(acc[mt][nt], af[mt][0],af[mt][1],af[mt][2],af[mt][3],
                     bl[nt*2], bl[nt*2+1]);
        }
    uint32_t aA = cx.aoffA ^ kso;
    #pragma unroll
    for (int mt = 0; mt < 4; mt++)
        ldm_x4(af[mt], cx.bAl + sA + aA + mt*1024);
    #pragma unroll
    for (int mt = 0; mt < 4; mt++)
        #pragma unroll
        for (int nt = 0; nt < 4; nt++)
            mma_bf16(acc[mt][nt], af[mt][0],af[mt][1],af[mt][2],af[mt][3],
                     bh[nt*2], bh[nt*2+1]);
}

// Pipeline invariants (one barrier/iter, race-free) — see R15 notes.
__device__ __forceinline__ void gemm_mainloop(GemmCtx& cx, float acc[4][4][4]) {
    const int NITER = DMODEL / BK;   // 32
    gemm_issue(cx, 0, 0);
    gemm_issue(cx, 1, BK);
    cp_wait<1>();
    __syncthreads();

    uint32_t af[4][4], bh[8], bl[8];
    gemm_load_frag(cx, 0, 0, af, bh, bl);

    int st = 0;
    for (int it = 0; it < NITER; it++) {
        uint32_t sA = (uint32_t)st * STG;
        int st1 = (st + 1 == NSTAGE) ? 0 : st + 1;
        int st2 = (st1 + 1 == NSTAGE) ? 0 : st1 + 1;

        gemm_mma_group(cx, sA, 0, af, bh, bl, acc);
        gemm_load_frag(cx, sA, 32, af, bh, bl);
        cp_wait<0>();
        __syncthreads();
        if (it + 2 < NITER) gemm_issue(cx, st2, (it+2)*BK);
        gemm_mma_group(cx, sA, 32, af, bh, bl, acc);
        if (it + 1 < NITER)
            gemm_load_frag(cx, (uint32_t)st1 * STG, 0, af, bh, bl);
        st = st1;
    }
}

// full GEMM body with bf16 hi/lo split epilogue (used by gemm_w and fused Q)
__device__ __forceinline__ void gemm_body_split(
    int row0, int col0, int tid, char* smem,
    const __nv_bfloat16* Ahg, const __nv_bfloat16* Alg,
    const __nv_bfloat16* BTh, const __nv_bfloat16* BTl,
    const float* bias, bool elu,
    __nv_bfloat16* H, __nv_bfloat16* L)
{
    GemmCtx cx;
    gemm_ctx_init(cx, s2u(smem), row0, col0, tid, Ahg, Alg, BTh, BTl);

    float acc[4][4][4];
    #pragma unroll
    for (int i = 0; i < 4; i++)
        #pragma unroll
        for (int j = 0; j < 4; j++)
            #pragma unroll
            for (int e = 0; e < 4; e++) acc[i][j][e] = 0.f;

    gemm_mainloop(cx, acc);

    int w = tid >> 5, lane = tid & 31;
    int wm = (w & 1) * 64, wn = (w >> 1) * 32;
    int g = lane >> 2, tq = lane & 3;
    #pragma unroll
    for (int mt = 0; mt < 4; mt++) {
        #pragma unroll
        for (int nt = 0; nt < 4; nt++) {
            int r = row0 + wm + mt*16 + g;
            int c = col0 + wn + nt*8 + tq*2;
            float b0 = bias[c], b1 = bias[c+1];
            #pragma unroll
            for (int h = 0; h < 2; h++) {
                int rr = r + h*8;
                float v0 = acc[mt][nt][h*2+0] + b0;
                float v1 = acc[mt][nt][h*2+1] + b1;
                if (elu) {
                    v0 = (v0 > 0.f) ? v0 : expm1f(v0);
                    v1 = (v1 > 0.f) ? v1 : expm1f(v1);
                }
                __nv_bfloat16 h0,l0,h1,l1;
                split2(v0,h0,l0); split2(v1,h1,l1);
                size_t idx = (size_t)rr*DMODEL + c;
                *(uint32_t*)&H[idx] = pack2(h0,h1);
                *(uint32_t*)&L[idx] = pack2(l0,l1);
            }
        }
    }
}

// ---------------- K/V GEMMs (grid.z = 0,1 -> wz = 1,2) ---------------------
__global__ __launch_bounds__(256, 2) void gemm_w(
    const __nv_bfloat16* __restrict__ Ahg, const __nv_bfloat16* __restrict__ Alg,
    const __nv_bfloat16* __restrict__ WTh, const __nv_bfloat16* __restrict__ WTl,
    const float* __restrict__ bk, const float* __restrict__ bv,
    __nv_bfloat16* __restrict__ Kh, __nv_bfloat16* __restrict__ Kl,
    __nv_bfloat16* __restrict__ Vh, __nv_bfloat16* __restrict__ Vl)
{
    extern __shared__ __align__(1024) char smem[];
    int wz = blockIdx.z + 1;   // 1 = K, 2 = V
    const size_t WSZ = (size_t)DMODEL*DMODEL;
    const float* bias = (wz == 1) ? bk : bv;
    __nv_bfloat16* H = (wz == 1) ? Kh : Vh;
    __nv_bfloat16* L = (wz == 1) ? Kl : Vl;
    gemm_body_split(blockIdx.y*BM, blockIdx.x*BN, threadIdx.x, smem,
                    Ahg, Alg, WTh + wz*WSZ, WTl + wz*WSZ,
                    bias, wz == 1, H, L);
}

// ---------------- fused: Q GEMM (blocks 0..1023) + kv_ksum (1024..1535) ----
#define KVP 144
#define KVT_TILE (32*KVP)
#define KVT_STG  (4*KVT_TILE)          // 18432 per stage

__global__ __launch_bounds__(256, 2) void gemm_q_kv(
    const __nv_bfloat16* __restrict__ Ahg, const __nv_bfloat16* __restrict__ Alg,
    const __nv_bfloat16* __restrict__ WTh, const __nv_bfloat16* __restrict__ WTl,
    const float* __restrict__ bq,
    __nv_bfloat16* __restrict__ Qh, __nv_bfloat16* __restrict__ Ql,
    const __nv_bfloat16* __restrict__ Kh_, const __nv_bfloat16* __restrict__ Kl_,
    const __nv_bfloat16* __restrict__ Vh_, const __nv_bfloat16* __restrict__ Vl_,
    float* __restrict__ KVg, float* __restrict__ Ksumg)
{
    extern __shared__ __align__(1024) char smem[];
    int bid = blockIdx.x;
    int tid = threadIdx.x;

    if (bid < 1024) {
        // ---- Q projection tile ----
        int col0 = (bid & 7) * BN;
        int row0 = (bid >> 3) * BM;
        gemm_body_split(row0, col0, tid, smem, Ahg, Alg, WTh, WTl,
                        bq, true, Qh, Ql);
        return;
    }

    // ---- kv_ksum chunk (256 threads: 8 warps, each owns one hh-half) ----
    uint32_t sb = s2u(smem);
    int idx = bid - 1024;
    int bh  = idx >> 3;              // 0..63
    int nbase = (idx & 7) * (SEQ / NCHUNK);
    int b   = bh >> 4, h = bh & 15;
    int w   = tid >> 5, lane = tid & 31;
    int hw  = w >> 2;                // hh half 0/1
    int wm  = (w & 1) * 32;
    int wn  = ((w >> 1) & 1) * 32;

    const size_t rb = (size_t)b * SEQ * DMODEL + (size_t)nbase * DMODEL
                    + (size_t)h * HDIM;
    const __nv_bfloat16* src[4] = {Kh_ + rb, Kl_ + rb, Vh_ + rb, Vl_ + rb};

    uint32_t arowA = (uint32_t)((lane & 7) + ((lane >> 4) & 1) * 8);
    uint32_t acolA = (uint32_t)((wm + ((lane >> 3) & 1) * 8) * 2);
    uint32_t arowB = (uint32_t)((lane & 7) + ((lane >> 3) & 1) * 8);
    uint32_t acolB = (uint32_t)((wn + ((lane >> 4) & 1) * 8) * 2);

    float acc[2][4][4] = {};
    float aks[2][4]    = {};
    const uint32_t ONES = 0x3F803F80u;

    auto issue = [&](int st, int n0) {
        #pragma unroll
        for (int i = 0; i < 4; i++) {          // 4 chunks/thread @256 thr
            int t = i;
            int r = tid >> 3;
            int c = tid & 7;
            cp16(sb + st*KVT_STG + t*KVT_TILE + r*KVP + c*16,
                 src[t] + (size_t)(n0 + r) * DMODEL + c*8);
        }
        cp_commit();
    };

    const int NS = (SEQ / NCHUNK) / 32;   // 16
    issue(0, 0); issue(1, 32);
    int st = 0;
    for (int it = 0; it < NS; it++) {
        if (it == NS-1) cp_wait<0>(); else cp_wait<1>();
        __syncthreads();
        uint32_t S = sb + st*KVT_STG;
        {
            uint32_t ro = (uint32_t)hw * 16 * KVP;
            uint32_t akh[2][4], akl[2][4], bvh[2][4], bvl[2][4];
            #pragma unroll
            for (int mt = 0; mt < 2; mt++) {
                uint32_t ad = ro + arowA*KVP + acolA + mt*32;
                ldm_x4t(akh[mt], S + 0*KVT_TILE + ad);
                ldm_x4t(akl[mt], S + 1*KVT_TILE + ad);
            }
            #pragma unroll
            for (int et = 0; et < 2; et++) {
                uint32_t ad = ro + arowB*KVP + acolB + et*32;
                ldm_x4t(bvh[et], S + 2*KVT_TILE + ad);
                ldm_x4t(bvl[et], S + 3*KVT_TILE + ad);
            }
            #pragma unroll
            for (int mt = 0; mt < 2; mt++) {
                #pragma unroll
                for (int nt = 0; nt < 4; nt++) {
                    uint32_t h0 = bvh[nt>>1][(nt&1)*2], h1 = bvh[nt>>1][(nt&1)*2+1];
                    uint32_t l0 = bvl[nt>>1][(nt&1)*2], l1 = bvl[nt>>1][(nt&1)*2+1];
                    mma_bf16(acc[mt][nt], akh[mt][0],akh[mt][1],akh[mt][2],akh[mt][3], h0,h1);
                    mma_bf16(acc[mt][nt], akh[mt][0],akh[mt][1],akh[mt][2],akh[mt][3], l0,l1);
                    mma_bf16(acc[mt][nt], akl[mt][0],akl[mt][1],akl[mt][2],akl[mt][3], h0,h1);
                }
                if (wn == 0) {
                    mma_bf16(aks[mt], akh[mt][0],akh[mt][1],akh[mt][2],akh[mt][3], ONES, ONES);
                    mma_bf16(aks[mt], akl[mt][0],akl[mt][1],akl[mt][2],akl[mt][3], ONES, ONES);
                }
            }
        }
        __syncthreads();
        if (it + 2 < NS) issue(st, (it+2)*32);
        st ^= 1;
    }

    float* KVb = KVg + (size_t)bh*HDIM*HDIM;
    #pragma unroll
    for (int mt = 0; mt < 2; mt++)
        #pragma unroll
        for (int nt = 0; nt < 4; nt++) {
            int d0 = wm + mt*16 + (lane >> 2);
            int e0 = wn + nt*8 + (lane & 3)*2;
            atomicAdd(&KVb[d0*HDIM + e0],         acc[mt][nt][0]);
            atomicAdd(&KVb[d0*HDIM + e0 + 1],     acc[mt][nt][1]);
            atomicAdd(&KVb[(d0+8)*HDIM + e0],     acc[mt][nt][2]);
            atomicAdd(&KVb[(d0+8)*HDIM + e0 + 1], acc[mt][nt][3]);
        }
    if (wn == 0 && (lane & 3) == 0) {
        #pragma unroll
        for (int mt = 0; mt < 2; mt++) {
            int d0 = wm + mt*16 + (lane >> 2);
            atomicAdd(&Ksumg[bh*HDIM + d0],     aks[mt][0]);
            atomicAdd(&Ksumg[bh*HDIM + d0 + 8], aks[mt][2]);
        }
    }
}

// ---------------- final GEMM: Y = x + attn @ Wo + bo -----------------------
__global__ __launch_bounds__(256, 2) void gemm_out(
    const __nv_bfloat16* __restrict__ Ahg, const __nv_bfloat16* __restrict__ Alg,
    const __nv_bfloat16* __restrict__ BTh, const __nv_bfloat16* __restrict__ BTl,
    const float* __restrict__ bias, const float* __restrict__ res,
    float* __restrict__ C)
{
    extern __shared__ __align__(1024) char smem[];
    int tid  = threadIdx.x;
    int row0 = blockIdx.y * BM;
    int col0 = blockIdx.x * BN;

    GemmCtx cx;
    gemm_ctx_init(cx, s2u(smem), row0, col0, tid, Ahg, Alg, BTh, BTl);

    float acc[4][4][4];
    #pragma unroll
    for (int i = 0; i < 4; i++)
        #pragma unroll
        for (int j = 0; j < 4; j++)
            #pragma unroll
            for (int e = 0; e < 4; e++) acc[i][j][e] = 0.f;

    gemm_mainloop(cx, acc);

    int w = tid >> 5, lane = tid & 31;
    int wm = (w & 1) * 64, wn = (w >> 1) * 32;
    int g = lane >> 2, tq = lane & 3;
    #pragma unroll
    for (int mt = 0; mt < 4; mt++) {
        #pragma unroll
        for (int nt = 0; nt < 4; nt++) {
            int r = row0 + wm + mt*16 + g;
            int c = col0 + wn + nt*8 + tq*2;
            float b0 = bias[c], b1 = bias[c+1];
            #pragma unroll
            for (int h = 0; h < 2; h++) {
                int rr = r + h*8;
                const float2 rv = *(const float2*)&res[(size_t)rr*DMODEL + c];
                float v0 = acc[mt][nt][h*2+0] + b0 + rv.x;
                float v1 = acc[mt][nt][h*2+1] + b1 + rv.y;
                *(float2*)&C[(size_t)rr*DMODEL + c] = make_float2(v0, v1);
            }
        }
    }
}

// ---------------- kvt_fin: KV fp32 [d][e] -> KVT split [e][d] --------------
__global__ __launch_bounds__(128) void kvt_fin(
    const float* __restrict__ KVg,
    __nv_bfloat16* __restrict__ KVTh, __nv_bfloat16* __restrict__ KVTl)
{
    int bh = blockIdx.x, tid = threadIdx.x;
    const float* KVb = KVg + (size_t)bh*HDIM*HDIM;
    int e = tid >> 1, dh = (tid & 1) * 32;
    #pragma unroll
    for (int j = 0; j < 32; j += 2) {
        int d = dh + j;
        float v0 = KVb[d*HDIM + e], v1 = KVb[(d+1)*HDIM + e];
        __nv_bfloat16 h0,l0,h1,l1;
        split2(v0,h0,l0); split2(v1,h1,l1);
        size_t idx = (size_t)bh*HDIM*HDIM + (size_t)e*HDIM + d;
        *(uint32_t*)&KVTh[idx] = pack2(h0,h1);
        *(uint32_t*)&KVTl[idx] = pack2(l0,l1);
    }
}

// ---------------- qattn_t: attn = z * (Q @ KV), tensor, split output -------
#define QAP 144
#define QSM (2*128*QAP + 2*64*QAP + 256 + 512)

__global__ __launch_bounds__(256) void qattn_t(
    const __nv_bfloat16* __restrict__ Qh_, const __nv_bfloat16* __restrict__ Ql_,
    const __nv_bfloat16* __restrict__ KVTh, const __nv_bfloat16* __restrict__ KVTl,
    const float* __restrict__ Ksumg,
    __nv_bfloat16* __restrict__ AttH, __nv_bfloat16* __restrict__ AttL)
{
    extern __shared__ __align__(16) char smem[];
    uint32_t sb = s2u(smem);
    int tid = threadIdx.x;
    int bh  = blockIdx.y;
    int b   = bh >> 4, h = bh & 15;
    int n0  = blockIdx.x * 128;
    const size_t qb = (size_t)b*SEQ*DMODEL + (size_t)n0*DMODEL + (size_t)h*HDIM;

    const uint32_t oQh = 0, oQl = 128*QAP, oBh = 2*128*QAP,
                   oBl = 2*128*QAP + 64*QAP,
                   oKs = 2*128*QAP + 2*64*QAP,
                   oZ  = oKs + 256;

    #pragma unroll
    for (int i = 0; i < 4; i++) {
        int cid = tid + i*256; int r = cid >> 3, c = cid & 7;
        size_t go = qb + (size_t)r*DMODEL + c*8;
        cp16(sb + oQh + r*QAP + c*16, Qh_ + go);
        cp16(sb + oQl + r*QAP + c*16, Ql_ + go);
    }
    #pragma unroll
    for (int i = 0; i < 2; i++) {
        int cid = tid + i*256; int r = cid >> 3, c = cid & 7;
        size_t go = (size_t)bh*HDIM*HDIM + (size_t)r*HDIM + c*8;
        cp16(sb + oBh + r*QAP + c*16, KVTh + go);
        cp16(sb + oBl + r*QAP + c*16, KVTl + go);
    }
    if (tid < 16) cp16(sb + oKs + tid*16, Ksumg + bh*HDIM + tid*4);
    cp_commit(); cp_wait<0>(); __syncthreads();

    {
        int row = tid >> 1, hf = (tid & 1) * 32;
        const __nv_bfloat16* qh = (const __nv_bfloat16*)(smem + oQh + row*QAP) + hf;
        const __nv_bfloat16* ql = (const __nv_bfloat16*)(smem + oQl + row*QAP) + hf;
        const float* ks = (const float*)(smem + oKs) + hf;
        float s = 0.f;
        #pragma unroll
        for (int j = 0; j < 32; j++) {
            float q = __bfloat162float(qh[j]) + __bfloat162float(ql[j]);
            s += q * ks[j];
        }
        s += __shfl_xor_sync(0xFFFFFFFFu, s, 1);
        if ((tid & 1) == 0) ((float*)(smem + oZ))[row] = 1.f / s;
    }
    __syncthreads();

    int w = tid >> 5, lane = tid & 31;
    int wm = (w & 3) * 32, wn = (w >> 2) * 32;
    uint32_t aA = (uint32_t)((wm + (lane & 15))*QAP + (lane >> 4)*16);
    uint32_t aB = (uint32_t)((wn + (lane & 7) + (lane >> 4)*8)*QAP + ((lane >> 3) & 1)*16);

    float acc[2][4][4] = {};
    #pragma unroll
    for (int ks2 = 0; ks2 < 4; ks2++) {
        uint32_t ko = (uint32_t)ks2 * 32;
        uint32_t aqh[2][4], aql[2][4], bkh[2][4], bkl[2][4];
        #pragma unroll
        for (int mt = 0; mt < 2; mt++) {
            ldm_x4(aqh[mt], sb + oQh + aA + mt*16*QAP + ko);
            ldm_x4(aql[mt], sb + oQl + aA + mt*16*QAP + ko);
        }
        #pragma unroll
        for (int et = 0; et < 2; et++) {
            ldm_x4(bkh[et], sb + oBh + aB + et*16*QAP + ko);
            ldm_x4(bkl[et], sb + oBl + aB + et*16*QAP + ko);
        }
        #pragma unroll
        for (int mt = 0; mt < 2; mt++)
            #pragma unroll
            for (int nt = 0; nt < 4; nt++) {
                uint32_t h0 = bkh[nt>>1][(nt&1)*2], h1 = bkh[nt>>1][(nt&1)*2+1];
                uint32_t l0 = bkl[nt>>1][(nt&1)*2], l1 = bkl[nt>>1][(nt&1)*2+1];
                mma_bf16(acc[mt][nt], aqh[mt][0],aqh[mt][1],aqh[mt][2],aqh[mt][3], h0,h1);
                mma_bf16(acc[mt][nt], aqh[mt][0],aqh[mt][1],aqh[mt][2],aqh[mt][3], l0,l1);
                mma_bf16(acc[mt][nt], aql[mt][0],aql[mt][1],aql[mt][2],aql[mt][3], h0,h1);
            }
    }

    const float* zs = (const float*)(smem + oZ);
    #pragma unroll
    for (int mt = 0; mt < 2; mt++)
        #pragma unroll
        for (int nt = 0; nt < 4; nt++) {
            int r0 = wm + mt*16 + (lane >> 2);
            int e0 = wn + nt*8 + (lane & 3)*2;
            #pragma unroll
            for (int hg = 0; hg < 2; hg++) {
                int rr = r0 + hg*8;
                float z = zs[rr];
                float v0 = acc[mt][nt][hg*2+0] * z;
                float v1 = acc[mt][nt][hg*2+1] * z;
                __nv_bfloat16 h0,l0,h1,l1;
                split2(v0,h0,l0); split2(v1,h1,l1);
                size_t idx = qb + (size_t)rr*DMODEL + e0;
                *(uint32_t*)&AttH[idx] = pack2(h0,h1);
                *(uint32_t*)&AttL[idx] = pack2(l0,l1);
            }
        }
}

// ---------------- LayerNorm over D=1024 ------------------------------------
__global__ __launch_bounds__(256) void ln_k(
    const float* __restrict__ Y, const float* __restrict__ gamma,
    const float* __restrict__ beta, float* __restrict__ out)
{
    int row = blockIdx.x;
    int tid = threadIdx.x;
    float4 v = *(const float4*)&Y[(size_t)row*DMODEL + tid*4];
    float s  = v.x + v.y + v.z + v.w;
    float sq = v.x*v.x + v.y*v.y + v.z*v.z + v.w*v.w;
    #pragma unroll
    for (int o = 16; o > 0; o >>= 1) {
        s  += __shfl_xor_sync(0xFFFFFFFFu, s,  o);
        sq += __shfl_xor_sync(0xFFFFFFFFu, sq, o);
    }
    __shared__ float ss[8], ssq[8];
    int w = tid >> 5, l = tid & 31;
    if (l == 0) { ss[w] = s; ssq[w] = sq; }
    __syncthreads();
    if (tid == 0) {
        float S = 0.f, SQ = 0.f;
        #pragma unroll
        for (int i = 0; i < 8; i++) { S += ss[i]; SQ += ssq[i]; }
        ss[0] = S; ssq[0] = SQ;
    }
    __syncthreads();
    float mu  = ss[0] * (1.f/1024.f);
    float var = ssq[0] * (1.f/1024.f) - mu*mu;
    float inv = rsqrtf(var + 1e-3f);
    float4 gm = *(const float4*)&gamma[tid*4];
    float4 be = *(const float4*)&beta[tid*4];
    float4 o;
    o.x = (v.x - mu)*inv*gm.x + be.x;
    o.y = (v.y - mu)*inv*gm.y + be.y;
    o.z = (v.z - mu)*inv*gm.z + be.z;
    o.w = (v.w - mu)*inv*gm.w + be.w;
    *(float4*)&out[(size_t)row*DMODEL + tid*4] = o;
}

// ---------------- host entry ------------------------------------------------
extern "C" void kernel_launch(void* const* d_in, const int* in_sizes, int n_in,
                              void* d_out, int out_size)
{
    const float* x     = (const float*)d_in[0];
    const float* Wq    = (const float*)d_in[1];
    const float* bq    = (const float*)d_in[2];
    const float* Wk    = (const float*)d_in[3];
    const float* bk    = (const float*)d_in[4];
    const float* Wv    = (const float*)d_in[5];
    const float* bv    = (const float*)d_in[6];
    const float* Wo    = (const float*)d_in[7];
    const float* bo    = (const float*)d_in[8];
    const float* gamma = (const float*)d_in[9];
    const float* beta  = (const float*)d_in[10];
    float* out = (float*)d_out;

    float *Y, *KV, *Ksum;
    __nv_bfloat16 *Ah, *Al, *Qh, *Ql, *Kh, *Kl, *Vh, *Vl, *WTh, *WTl, *KVTh, *KVTl;
    cudaGetSymbolAddress((void**)&Y,    g_Y);
    cudaGetSymbolAddress((void**)&Ah,   g_Ah);
    cudaGetSymbolAddress((void**)&Al,   g_Al);
    cudaGetSymbolAddress((void**)&Qh,   g_Qh);
    cudaGetSymbolAddress((void**)&Ql,   g_Ql);
    cudaGetSymbolAddress((void**)&Kh,   g_Kh);
    cudaGetSymbolAddress((void**)&Kl,   g_Kl);
    cudaGetSymbolAddress((void**)&Vh,   g_Vh);
    cudaGetSymbolAddress((void**)&Vl,   g_Vl);
    cudaGetSymbolAddress((void**)&WTh,  g_WTh);
    cudaGetSymbolAddress((void**)&WTl,  g_WTl);
    cudaGetSymbolAddress((void**)&KV,   g_KV);
    cudaGetSymbolAddress((void**)&KVTh, g_KVTh);
    cudaGetSymbolAddress((void**)&KVTl, g_KVTl);
    cudaGetSymbolAddress((void**)&Ksum, g_Ksum);

    cudaFuncSetAttribute(gemm_w,    cudaFuncAttributeMaxDynamicSharedMemorySize, GSMEM);
    cudaFuncSetAttribute(gemm_q_kv, cudaFuncAttributeMaxDynamicSharedMemorySize, GSMEM);
    cudaFuncSetAttribute(gemm_out,  cudaFuncAttributeMaxDynamicSharedMemorySize, GSMEM);
    cudaFuncSetAttribute(qattn_t,   cudaFuncAttributeMaxDynamicSharedMemorySize, QSM);

    const size_t WSZ = (size_t)DMODEL*DMODEL;
    dim3 gkv(DMODEL/BN, MTOT/BM, 2);    // (8, 128, 2)
    dim3 gout(DMODEL/BN, MTOT/BM);      // (8, 128)

    // prep: weight split+transpose | x split | KV zero (wz order q,k,v,o)
    prep_k<<<7168, 256>>>(x, Wq, Wk, Wv, Wo, Ah, Al, WTh, WTl, KV, Ksum);

    gemm_w<<<gkv, 256, GSMEM>>>(Ah, Al, WTh, WTl, bk, bv, Kh, Kl, Vh, Vl);

    gemm_q_kv<<<1536, 256, GSMEM>>>(Ah, Al, WTh, WTl, bq, Qh, Ql,
                                    Kh, Kl, Vh, Vl, KV, Ksum);

    kvt_fin<<<BH, 128>>>(KV, KVTh, KVTl);
    qattn_t<<<dim3(SEQ/128, BH), 256, QSM>>>(Qh, Ql, KVTh, KVTl, Ksum, Ah, Al);

    gemm_out<<<gout, 256, GSMEM>>>(Ah, Al, WTh + 3*WSZ, WTl + 3*WSZ, bo, x, Y);

    ln_k<<<MTOT, 256>>>(Y, gamma, beta, out);
}

// round 17
// speedup vs baseline: 1.0057x; 1.0057x over previous
#include <cuda_runtime.h>
#include <cuda_bf16.h>
#include <math.h>
#include <stdint.h>

#define MTOT   16384      // B*N = 4*4096
#define DMODEL 1024
#define NHEADS 16
#define HDIM   64
#define BATCH  4
#define SEQ    4096
#define BH     (BATCH*NHEADS)   // 64
#define NCHUNK 8

// ---------------- scratch (device globals: allocation-free) ----------------
__device__ float g_Y[(size_t)MTOT*DMODEL];
__device__ __nv_bfloat16 g_Ah[(size_t)MTOT*DMODEL];
__device__ __nv_bfloat16 g_Al[(size_t)MTOT*DMODEL];
__device__ __nv_bfloat16 g_Qh[(size_t)MTOT*DMODEL];
__device__ __nv_bfloat16 g_Ql[(size_t)MTOT*DMODEL];
__device__ __nv_bfloat16 g_Kh[(size_t)MTOT*DMODEL];
__device__ __nv_bfloat16 g_Kl[(size_t)MTOT*DMODEL];
__device__ __nv_bfloat16 g_Vh[(size_t)MTOT*DMODEL];
__device__ __nv_bfloat16 g_Vl[(size_t)MTOT*DMODEL];
__device__ __nv_bfloat16 g_WTh[4ULL*DMODEL*DMODEL];   // [w][n][k]
__device__ __nv_bfloat16 g_WTl[4ULL*DMODEL*DMODEL];
__device__ float g_KV[BH*HDIM*HDIM];                  // [bh][d][e] fp32 accum
__device__ float g_Ksum[BH*HDIM];

__device__ __forceinline__ void split2(float x, __nv_bfloat16& h, __nv_bfloat16& l) {
    h = __float2bfloat16_rn(x);
    l = __float2bfloat16_rn(x - __bfloat162float(h));
}
__device__ __forceinline__ uint32_t pack2(__nv_bfloat16 a, __nv_bfloat16 b) {
    __nv_bfloat162 t{a, b};
    return *(uint32_t*)&t;
}

// ---------------- PTX helpers ----------------------------------------------
__device__ __forceinline__ uint32_t s2u(const void* p) {
    uint32_t a;
    asm("{ .reg .u64 t; cvta.to.shared.u64 t, %1; cvt.u32.u64 %0, t; }"
        : "=r"(a) : "l"(p));
    return a;
}
__device__ __forceinline__ void cp16(uint32_t dst, const void* src) {
    asm volatile("cp.async.cg.shared.global [%0], [%1], 16;\n" :: "r"(dst), "l"(src));
}
__device__ __forceinline__ void cp_commit() { asm volatile("cp.async.commit_group;\n"); }
template<int N> __device__ __forceinline__ void cp_wait() {
    asm volatile("cp.async.wait_group %0;\n" :: "n"(N));
}
__device__ __forceinline__ void ldm_x4(uint32_t r[4], uint32_t addr) {
    asm volatile("ldmatrix.sync.aligned.m8n8.x4.shared.b16 {%0,%1,%2,%3}, [%4];"
        : "=r"(r[0]), "=r"(r[1]), "=r"(r[2]), "=r"(r[3]) : "r"(addr));
}
__device__ __forceinline__ void ldm_x4t(uint32_t r[4], uint32_t addr) {
    asm volatile("ldmatrix.sync.aligned.m8n8.x4.trans.shared.b16 {%0,%1,%2,%3}, [%4];"
        : "=r"(r[0]), "=r"(r[1]), "=r"(r[2]), "=r"(r[3]) : "r"(addr));
}
__device__ __forceinline__ void mma_bf16(float c[4],
    uint32_t a0, uint32_t a1, uint32_t a2, uint32_t a3, uint32_t b0, uint32_t b1) {
    asm volatile(
        "mma.sync.aligned.m16n8k16.row.col.f32.bf16.bf16.f32 "
        "{%0,%1,%2,%3}, {%4,%5,%6,%7}, {%8,%9}, {%0,%1,%2,%3};"
        : "+f"(c[0]), "+f"(c[1]), "+f"(c[2]), "+f"(c[3])
        : "r"(a0), "r"(a1), "r"(a2), "r"(a3), "r"(b0), "r"(b1));
}
__device__ __forceinline__ uint32_t sw64(uint32_t off) {
    return off ^ ((off >> 3) & 0x30);
}

// ---------------- prep: weight split+transpose | x split | zero KV ---------
__global__ __launch_bounds__(256) void prep_k(
    const float* __restrict__ x,
    const float* __restrict__ W0, const float* __restrict__ W1,
    const float* __restrict__ W2, const float* __restrict__ W3,
    __nv_bfloat16* __restrict__ Ah, __nv_bfloat16* __restrict__ Al,
    __nv_bfloat16* __restrict__ Th, __nv_bfloat16* __restrict__ Tl,
    float* __restrict__ KV, float* __restrict__ Ksum)
{
    __shared__ float tile[32][33];
    int b = blockIdx.x, tid = threadIdx.x;
    if (b < 4096) {
        int wz = b >> 10;
        int n0 = (b & 31) * 32;
        int k0 = ((b >> 5) & 31) * 32;
        int tx = tid & 31, ty = tid >> 5;   // (32, 8)
        const float* W = (wz == 0) ? W0 : (wz == 1) ? W1 : (wz == 2) ? W2 : W3;
        const size_t WSZ = (size_t)DMODEL*DMODEL;
        #pragma unroll
        for (int i = 0; i < 32; i += 8)
            tile[ty+i][tx] = W[(size_t)(k0+ty+i)*DMODEL + n0 + tx];
        __syncthreads();
        #pragma unroll
        for (int i = 0; i < 32; i += 8) {
            float v = tile[tx][ty+i];
            __nv_bfloat16 h, l; split2(v, h, l);
            size_t o = wz*WSZ + (size_t)(n0+ty+i)*DMODEL + k0 + tx;
            Th[o] = h; Tl[o] = l;
        }
    } else if (b < 6144) {
        const int n4 = MTOT*DMODEL/4;
        for (int i = (b-4096)*256 + tid; i < n4; i += 2048*256) {
            float4 v = ((const float4*)x)[i];
            __nv_bfloat16 h0,h1,h2,h3,l0,l1,l2,l3;
            split2(v.x,h0,l0); split2(v.y,h1,l1); split2(v.z,h2,l2); split2(v.w,h3,l3);
            __nv_bfloat162* Hp = (__nv_bfloat162*)Ah;
            __nv_bfloat162* Lp = (__nv_bfloat162*)Al;
            Hp[i*2+0] = __nv_bfloat162{h0,h1}; Hp[i*2+1] = __nv_bfloat162{h2,h3};
            Lp[i*2+0] = __nv_bfloat162{l0,l1}; Lp[i*2+1] = __nv_bfloat162{l2,l3};
        }
    } else {
        int i = (b-6144)*256 + tid;
        if (i < BH*HDIM*HDIM) KV[i] = 0.f;
        if (i < BH*HDIM)      Ksum[i] = 0.f;
    }
}

// ---------------- bf16-split dense GEMM core (3-stage, pipelined) ----------
#define BM 128
#define BN 128
#define BK 32
#define STG 8192
#define NSTAGE 3
#define BUFSZ (NSTAGE*STG)
#define GSMEM (4*BUFSZ)              // 98304

struct GemmCtx {
    uint32_t bAh, bAl, bBh, bBl;
    uint32_t aoffA, aoffB;
    uint32_t d0sw, d1sw;
    const __nv_bfloat16 *AhR, *AlR, *BhR, *BlR;
    size_t g0, g1;
};

__device__ __forceinline__ void gemm_ctx_init(GemmCtx& cx, uint32_t sb,
    int row0, int col0, int tid,
    const __nv_bfloat16* Ahg, const __nv_bfloat16* Alg,
    const __nv_bfloat16* BTh, const __nv_bfloat16* BTl)
{
    cx.bAh = sb + 0*BUFSZ;  cx.bAl = sb + 1*BUFSZ;
    cx.bBh = sb + 2*BUFSZ;  cx.bBl = sb + 3*BUFSZ;
    int w = tid >> 5, lane = tid & 31;
    int wm = (w & 1) * 64, wn = (w >> 1) * 32;
    uint32_t linA = (uint32_t)((wm + (lane & 15)) * 64 + (lane >> 4) * 16);
    cx.aoffA = sw64(linA);
    uint32_t linB = (uint32_t)((wn + (lane & 7) + ((lane >> 4) << 3)) * 64 +
                               ((lane >> 3) & 1) * 16);
    cx.aoffB = sw64(linB);
    int r0 = tid >> 2,          c0 = tid & 3;
    int r1 = (tid + 256) >> 2,  c1 = (tid + 256) & 3;
    cx.d0sw = sw64((uint32_t)(r0*64 + c0*16));
    cx.d1sw = sw64((uint32_t)(r1*64 + c1*16));
    cx.g0 = (size_t)r0*DMODEL + c0*8;
    cx.g1 = (size_t)r1*DMODEL + c1*8;
    cx.AhR = Ahg + (size_t)row0 * DMODEL;
    cx.AlR = Alg + (size_t)row0 * DMODEL;
    cx.BhR = BTh + (size_t)col0 * DMODEL;
    cx.BlR = BTl + (size_t)col0 * DMODEL;
}

__device__ __forceinline__ void gemm_issue(GemmCtx& cx, int st, int k0) {
    uint32_t s = (uint32_t)st * STG;
    cp16(cx.bAh + s + cx.d0sw, cx.AhR + cx.g0 + k0);
    cp16(cx.bAh + s + cx.d1sw, cx.AhR + cx.g1 + k0);
    cp16(cx.bAl + s + cx.d0sw, cx.AlR + cx.g0 + k0);
    cp16(cx.bAl + s + cx.d1sw, cx.AlR + cx.g1 + k0);
    cp16(cx.bBh + s + cx.d0sw, cx.BhR + cx.g0 + k0);
    cp16(cx.bBh + s + cx.d1sw, cx.BhR + cx.g1 + k0);
    cp16(cx.bBl + s + cx.d0sw, cx.BlR + cx.g0 + k0);
    cp16(cx.bBl + s + cx.d1sw, cx.BlR + cx.g1 + k0);
    cp_commit();
}

__device__ __forceinline__ void gemm_load_frag(GemmCtx& cx, uint32_t sA, uint32_t kso,
    uint32_t af[4][4], uint32_t bh[8], uint32_t bl[8])
{
    uint32_t aA = cx.aoffA ^ kso;
    uint32_t aB = cx.aoffB ^ kso;
    #pragma unroll
    for (int p = 0; p < 2; p++) {
        ldm_x4(&bh[p*4], cx.bBh + sA + aB + p*1024);
        ldm_x4(&bl[p*4], cx.bBl + sA + aB + p*1024);
    }
    #pragma unroll
    for (int mt = 0; mt < 4; mt++)
        ldm_x4(af[mt], cx.bAh + sA + aA + mt*1024);
}

__device__ __forceinline__ void gemm_mma_group(GemmCtx& cx, uint32_t sA, uint32_t kso,
    uint32_t af[4][4], uint32_t bh[8], uint32_t bl[8], float acc[4][4][4])
{
    #pragma unroll
    for (int mt = 0; mt < 4; mt++)
        #pragma unroll
        for (int nt = 0; nt < 4; nt++) {
            mma_bf16(acc[mt][nt], af[mt][0],af[mt][1],af[mt][2],af[mt][3],
                     bh[nt*2], bh[nt*2+1]);
            mma_bf16(acc[mt][nt], af[mt][0],af[mt][1],af[mt][2],af[mt][3],
                     bl[nt*2], bl[nt*2+1]);
        }
    uint32_t aA = cx.aoffA ^ kso;
    #pragma unroll
    for (int mt = 0; mt < 4; mt++)
        ldm_x4(af[mt], cx.bAl + sA + aA + mt*1024);
    #pragma unroll
    for (int mt = 0; mt < 4; mt++)
        #pragma unroll
        for (int nt = 0; nt < 4; nt++)
            mma_bf16(acc[mt][nt], af[mt][0],af[mt][1],af[mt][2],af[mt][3],
                     bh[nt*2], bh[nt*2+1]);
}

// Pipeline invariants (one barrier/iter, race-free) — see R15 notes.
__device__ __forceinline__ void gemm_mainloop(GemmCtx& cx, float acc[4][4][4]) {
    const int NITER = DMODEL / BK;   // 32
    gemm_issue(cx, 0, 0);
    gemm_issue(cx, 1, BK);
    cp_wait<1>();
    __syncthreads();

    uint32_t af[4][4], bh[8], bl[8];
    gemm_load_frag(cx, 0, 0, af, bh, bl);

    int st = 0;
    for (int it = 0; it < NITER; it++) {
        uint32_t sA = (uint32_t)st * STG;
        int st1 = (st + 1 == NSTAGE) ? 0 : st + 1;
        int st2 = (st1 + 1 == NSTAGE) ? 0 : st1 + 1;

        gemm_mma_group(cx, sA, 0, af, bh, bl, acc);
        gemm_load_frag(cx, sA, 32, af, bh, bl);
        cp_wait<0>();
        __syncthreads();
        if (it + 2 < NITER) gemm_issue(cx, st2, (it+2)*BK);
        gemm_mma_group(cx, sA, 32, af, bh, bl, acc);
        if (it + 1 < NITER)
            gemm_load_frag(cx, (uint32_t)st1 * STG, 0, af, bh, bl);
        st = st1;
    }
}

// ---------------- merged Q/K/V GEMM: writes bf16 hi/lo outputs -------------
__global__ __launch_bounds__(256, 2) void gemm_qkv(
    const __nv_bfloat16* __restrict__ Ahg, const __nv_bfloat16* __restrict__ Alg,
    const __nv_bfloat16* __restrict__ WTh, const __nv_bfloat16* __restrict__ WTl,
    const float* __restrict__ bq, const float* __restrict__ bk,
    const float* __restrict__ bv,
    __nv_bfloat16* __restrict__ Qh, __nv_bfloat16* __restrict__ Ql,
    __nv_bfloat16* __restrict__ Kh, __nv_bfloat16* __restrict__ Kl,
    __nv_bfloat16* __restrict__ Vh, __nv_bfloat16* __restrict__ Vl)
{
    extern __shared__ __align__(1024) char smem[];
    int tid  = threadIdx.x;
    int row0 = blockIdx.y * BM;
    int col0 = blockIdx.x * BN;
    int wz   = blockIdx.z;
    const size_t WSZ = (size_t)DMODEL*DMODEL;
    const float* bias = (wz == 0) ? bq : (wz == 1) ? bk : bv;
    __nv_bfloat16* H = (wz == 0) ? Qh : (wz == 1) ? Kh : Vh;
    __nv_bfloat16* L = (wz == 0) ? Ql : (wz == 1) ? Kl : Vl;
    bool elu = (wz < 2);

    GemmCtx cx;
    gemm_ctx_init(cx, s2u(smem), row0, col0, tid,
                  Ahg, Alg, WTh + wz*WSZ, WTl + wz*WSZ);

    float acc[4][4][4];
    #pragma unroll
    for (int i = 0; i < 4; i++)
        #pragma unroll
        for (int j = 0; j < 4; j++)
            #pragma unroll
            for (int e = 0; e < 4; e++) acc[i][j][e] = 0.f;

    gemm_mainloop(cx, acc);

    int w = tid >> 5, lane = tid & 31;
    int wm = (w & 1) * 64, wn = (w >> 1) * 32;
    int g = lane >> 2, tq = lane & 3;
    #pragma unroll
    for (int mt = 0; mt < 4; mt++) {
        #pragma unroll
        for (int nt = 0; nt < 4; nt++) {
            int r = row0 + wm + mt*16 + g;
            int c = col0 + wn + nt*8 + tq*2;
            float b0 = bias[c], b1 = bias[c+1];
            #pragma unroll
            for (int h = 0; h < 2; h++) {
                int rr = r + h*8;
                float v0 = acc[mt][nt][h*2+0] + b0;
                float v1 = acc[mt][nt][h*2+1] + b1;
                if (elu) {
                    v0 = (v0 > 0.f) ? v0 : expm1f(v0);
                    v1 = (v1 > 0.f) ? v1 : expm1f(v1);
                }
                __nv_bfloat16 h0,l0,h1,l1;
                split2(v0,h0,l0); split2(v1,h1,l1);
                size_t idx = (size_t)rr*DMODEL + c;
                *(uint32_t*)&H[idx] = pack2(h0,h1);
                *(uint32_t*)&L[idx] = pack2(l0,l1);
            }
        }
    }
}

// ---------------- final GEMM: Y = x + attn @ Wo + bo -----------------------
__global__ __launch_bounds__(256, 2) void gemm_out(
    const __nv_bfloat16* __restrict__ Ahg, const __nv_bfloat16* __restrict__ Alg,
    const __nv_bfloat16* __restrict__ BTh, const __nv_bfloat16* __restrict__ BTl,
    const float* __restrict__ bias, const float* __restrict__ res,
    float* __restrict__ C)
{
    extern __shared__ __align__(1024) char smem[];
    int tid  = threadIdx.x;
    int row0 = blockIdx.y * BM;
    int col0 = blockIdx.x * BN;

    GemmCtx cx;
    gemm_ctx_init(cx, s2u(smem), row0, col0, tid, Ahg, Alg, BTh, BTl);

    float acc[4][4][4];
    #pragma unroll
    for (int i = 0; i < 4; i++)
        #pragma unroll
        for (int j = 0; j < 4; j++)
            #pragma unroll
            for (int e = 0; e < 4; e++) acc[i][j][e] = 0.f;

    gemm_mainloop(cx, acc);

    int w = tid >> 5, lane = tid & 31;
    int wm = (w & 1) * 64, wn = (w >> 1) * 32;
    int g = lane >> 2, tq = lane & 3;
    #pragma unroll
    for (int mt = 0; mt < 4; mt++) {
        #pragma unroll
        for (int nt = 0; nt < 4; nt++) {
            int r = row0 + wm + mt*16 + g;
            int c = col0 + wn + nt*8 + tq*2;
            float b0 = bias[c], b1 = bias[c+1];
            #pragma unroll
            for (int h = 0; h < 2; h++) {
                int rr = r + h*8;
                const float2 rv = *(const float2*)&res[(size_t)rr*DMODEL + c];
                float v0 = acc[mt][nt][h*2+0] + b0 + rv.x;
                float v1 = acc[mt][nt][h*2+1] + b1 + rv.y;
                *(float2*)&C[(size_t)rr*DMODEL + c] = make_float2(v0, v1);
            }
        }
    }
}

// ---------------- kv_ksum_t: chunked tensor KV accumulation ---------------
#define KVP 144
#define KVT_TILE (32*KVP)
#define KVT_STG  (4*KVT_TILE)          // 18432 per stage

__global__ __launch_bounds__(128) void kv_ksum_t(
    const __nv_bfloat16* __restrict__ Kh_, const __nv_bfloat16* __restrict__ Kl_,
    const __nv_bfloat16* __restrict__ Vh_, const __nv_bfloat16* __restrict__ Vl_,
    float* __restrict__ KVg, float* __restrict__ Ksumg)
{
    __shared__ __align__(16) char smem[2*KVT_STG];
    uint32_t sb = s2u(smem);
    int tid = threadIdx.x;
    int bh  = blockIdx.y;
    int b   = bh >> 4, h = bh & 15;
    int nbase = blockIdx.x * (SEQ / NCHUNK);   // 512-row chunk
    int w   = tid >> 5, lane = tid & 31;
    int wm  = (w & 1) * 32, wn = (w >> 1) * 32;

    const size_t rb = (size_t)b * SEQ * DMODEL + (size_t)nbase * DMODEL
                    + (size_t)h * HDIM;
    const __nv_bfloat16* src[4] = {Kh_ + rb, Kl_ + rb, Vh_ + rb, Vl_ + rb};

    uint32_t arowA = (uint32_t)((lane & 7) + ((lane >> 4) & 1) * 8);
    uint32_t acolA = (uint32_t)((wm + ((lane >> 3) & 1) * 8) * 2);
    uint32_t arowB = (uint32_t)((lane & 7) + ((lane >> 3) & 1) * 8);
    uint32_t acolB = (uint32_t)((wn + ((lane >> 4) & 1) * 8) * 2);

    float acc[2][4][4] = {};
    float aks[2][4]    = {};
    const uint32_t ONES = 0x3F803F80u;

    auto issue = [&](int st, int n0) {
        #pragma unroll
        for (int i = 0; i < 8; i++) {
            int t = i >> 1;
            int r = (i & 1) * 16 + (tid >> 3);
            int c = tid & 7;
            cp16(sb + st*KVT_STG + t*KVT_TILE + r*KVP + c*16,
                 src[t] + (size_t)(n0 + r) * DMODEL + c*8);
        }
        cp_commit();
    };

    const int NS = (SEQ / NCHUNK) / 32;   // 16
    issue(0, 0); issue(1, 32);
    int st = 0;
    for (int it = 0; it < NS; it++) {
        if (it == NS-1) cp_wait<0>(); else cp_wait<1>();
        __syncthreads();
        uint32_t S = sb + st*KVT_STG;
        #pragma unroll
        for (int hh = 0; hh < 2; hh++) {
            uint32_t ro = (uint32_t)hh * 16 * KVP;
            uint32_t akh[2][4], akl[2][4], bvh[2][4], bvl[2][4];
            #pragma unroll
            for (int mt = 0; mt < 2; mt++) {
                uint32_t ad = ro + arowA*KVP + acolA + mt*32;
                ldm_x4t(akh[mt], S + 0*KVT_TILE + ad);
                ldm_x4t(akl[mt], S + 1*KVT_TILE + ad);
            }
            #pragma unroll
            for (int et = 0; et < 2; et++) {
                uint32_t ad = ro + arowB*KVP + acolB + et*32;
                ldm_x4t(bvh[et], S + 2*KVT_TILE + ad);
                ldm_x4t(bvl[et], S + 3*KVT_TILE + ad);
            }
            #pragma unroll
            for (int mt = 0; mt < 2; mt++) {
                #pragma unroll
                for (int nt = 0; nt < 4; nt++) {
                    uint32_t h0 = bvh[nt>>1][(nt&1)*2], h1 = bvh[nt>>1][(nt&1)*2+1];
                    uint32_t l0 = bvl[nt>>1][(nt&1)*2], l1 = bvl[nt>>1][(nt&1)*2+1];
                    mma_bf16(acc[mt][nt], akh[mt][0],akh[mt][1],akh[mt][2],akh[mt][3], h0,h1);
                    mma_bf16(acc[mt][nt], akh[mt][0],akh[mt][1],akh[mt][2],akh[mt][3], l0,l1);
                    mma_bf16(acc[mt][nt], akl[mt][0],akl[mt][1],akl[mt][2],akl[mt][3], h0,h1);
                }
                if (wn == 0) {
                    mma_bf16(aks[mt], akh[mt][0],akh[mt][1],akh[mt][2],akh[mt][3], ONES, ONES);
                    mma_bf16(aks[mt], akl[mt][0],akl[mt][1],akl[mt][2],akl[mt][3], ONES, ONES);
                }
            }
        }
        __syncthreads();
        if (it + 2 < NS) issue(st, (it+2)*32);
        st ^= 1;
    }

    float* KVb = KVg + (size_t)bh*HDIM*HDIM;
    #pragma unroll
    for (int mt = 0; mt < 2; mt++)
        #pragma unroll
        for (int nt = 0; nt < 4; nt++) {
            int d0 = wm + mt*16 + (lane >> 2);
            int e0 = wn + nt*8 + (lane & 3)*2;
            atomicAdd(&KVb[d0*HDIM + e0],         acc[mt][nt][0]);
            atomicAdd(&KVb[d0*HDIM + e0 + 1],     acc[mt][nt][1]);
            atomicAdd(&KVb[(d0+8)*HDIM + e0],     acc[mt][nt][2]);
            atomicAdd(&KVb[(d0+8)*HDIM + e0 + 1], acc[mt][nt][3]);
        }
    if (wn == 0 && (lane & 3) == 0) {
        #pragma unroll
        for (int mt = 0; mt < 2; mt++) {
            int d0 = wm + mt*16 + (lane >> 2);
            atomicAdd(&Ksumg[bh*HDIM + d0],     aks[mt][0]);
            atomicAdd(&Ksumg[bh*HDIM + d0 + 8], aks[mt][2]);
        }
    }
}

// ---------------- qattn_t: attn = z*(Q@KV); inline KV split-transpose ------
#define QAP 144
#define QSM (2*128*QAP + 2*64*QAP + 256 + 512)

__global__ __launch_bounds__(256) void qattn_t(
    const __nv_bfloat16* __restrict__ Qh_, const __nv_bfloat16* __restrict__ Ql_,
    const float* __restrict__ KVg, const float* __restrict__ Ksumg,
    __nv_bfloat16* __restrict__ AttH, __nv_bfloat16* __restrict__ AttL)
{
    extern __shared__ __align__(16) char smem[];
    uint32_t sb = s2u(smem);
    int tid = threadIdx.x;
    int bh  = blockIdx.y;
    int b   = bh >> 4, h = bh & 15;
    int n0  = blockIdx.x * 128;
    const size_t qb = (size_t)b*SEQ*DMODEL + (size_t)n0*DMODEL + (size_t)h*HDIM;

    const uint32_t oQh = 0, oQl = 128*QAP, oBh = 2*128*QAP,
                   oBl = 2*128*QAP + 64*QAP,
                   oKs = 2*128*QAP + 2*64*QAP,
                   oZ  = oKs + 256;

    // Q tiles + fp32 KV (16 KB staged linearly into oBh..oBl region) + Ksum
    #pragma unroll
    for (int i = 0; i < 4; i++) {
        int cid = tid + i*256; int r = cid >> 3, c = cid & 7;
        size_t go = qb + (size_t)r*DMODEL + c*8;
        cp16(sb + oQh + r*QAP + c*16, Qh_ + go);
        cp16(sb + oQl + r*QAP + c*16, Ql_ + go);
    }
    const float* KVb = KVg + (size_t)bh*HDIM*HDIM;
    #pragma unroll
    for (int i = 0; i < 4; i++) {
        int ch = tid + i*256;          // 1024 chunks of 16B
        cp16(sb + oBh + ch*16, KVb + ch*4);
    }
    if (tid < 16) cp16(sb + oKs + tid*16, Ksumg + bh*HDIM + tid*4);
    cp_commit(); cp_wait<0>(); __syncthreads();

    // z = 1/(Q . Ksum) per row (2 threads/row)
    {
        int row = tid >> 1, hf = (tid & 1) * 32;
        const __nv_bfloat16* qh = (const __nv_bfloat16*)(smem + oQh + row*QAP) + hf;
        const __nv_bfloat16* ql = (const __nv_bfloat16*)(smem + oQl + row*QAP) + hf;
        const float* ks = (const float*)(smem + oKs) + hf;
        float s = 0.f;
        #pragma unroll
        for (int j = 0; j < 32; j++) {
            float q = __bfloat162float(qh[j]) + __bfloat162float(ql[j]);
            s += q * ks[j];
        }
        s += __shfl_xor_sync(0xFFFFFFFFu, s, 1);
        if ((tid & 1) == 0) ((float*)(smem + oZ))[row] = 1.f / s;
    }

    // stage fp32 KV[d][e] through registers, then write split KVT[e][d]
    float kvf[16];
    {
        int e = tid >> 2, d0 = (tid & 3) * 16;
        const float* KVs = (const float*)(smem + oBh);
        #pragma unroll
        for (int j = 0; j < 16; j++) kvf[j] = KVs[(d0 + j)*HDIM + e];
    }
    __syncthreads();   // all KV reads done; oZ visible
    {
        int e = tid >> 2, d0 = (tid & 3) * 16;
        __nv_bfloat16* Bh = (__nv_bfloat16*)(smem + oBh + e*QAP) + d0;
        __nv_bfloat16* Bl = (__nv_bfloat16*)(smem + oBl + e*QAP) + d0;
        #pragma unroll
        for (int j = 0; j < 16; j++) {
            __nv_bfloat16 hh, ll; split2(kvf[j], hh, ll);
            Bh[j] = hh; Bl[j] = ll;
        }
    }
    __syncthreads();

    int w = tid >> 5, lane = tid & 31;
    int wm = (w & 3) * 32, wn = (w >> 2) * 32;
    uint32_t aA = (uint32_t)((wm + (lane & 15))*QAP + (lane >> 4)*16);
    uint32_t aB = (uint32_t)((wn + (lane & 7) + (lane >> 4)*8)*QAP + ((lane >> 3) & 1)*16);

    float acc[2][4][4] = {};
    #pragma unroll
    for (int ks2 = 0; ks2 < 4; ks2++) {
        uint32_t ko = (uint32_t)ks2 * 32;
        uint32_t aqh[2][4], aql[2][4], bkh[2][4], bkl[2][4];
        #pragma unroll
        for (int mt = 0; mt < 2; mt++) {
            ldm_x4(aqh[mt], sb + oQh + aA + mt*16*QAP + ko);
            ldm_x4(aql[mt], sb + oQl + aA + mt*16*QAP + ko);
        }
        #pragma unroll
        for (int et = 0; et < 2; et++) {
            ldm_x4(bkh[et], sb + oBh + aB + et*16*QAP + ko);
            ldm_x4(bkl[et], sb + oBl + aB + et*16*QAP + ko);
        }
        #pragma unroll
        for (int mt = 0; mt < 2; mt++)
            #pragma unroll
            for (int nt = 0; nt < 4; nt++) {
                uint32_t h0 = bkh[nt>>1][(nt&1)*2], h1 = bkh[nt>>1][(nt&1)*2+1];
                uint32_t l0 = bkl[nt>>1][(nt&1)*2], l1 = bkl[nt>>1][(nt&1)*2+1];
                mma_bf16(acc[mt][nt], aqh[mt][0],aqh[mt][1],aqh[mt][2],aqh[mt][3], h0,h1);
                mma_bf16(acc[mt][nt], aqh[mt][0],aqh[mt][1],aqh[mt][2],aqh[mt][3], l0,l1);
                mma_bf16(acc[mt][nt], aql[mt][0],aql[mt][1],aql[mt][2],aql[mt][3], h0,h1);
            }
    }

    const float* zs = (const float*)(smem + oZ);
    #pragma unroll
    for (int mt = 0; mt < 2; mt++)
        #pragma unroll
        for (int nt = 0; nt < 4; nt++) {
            int r0 = wm + mt*16 + (lane >> 2);
            int e0 = wn + nt*8 + (lane & 3)*2;
            #pragma unroll
            for (int hg = 0; hg < 2; hg++) {
                int rr = r0 + hg*8;
                float z = zs[rr];
                float v0 = acc[mt][nt][hg*2+0] * z;
                float v1 = acc[mt][nt][hg*2+1] * z;
                __nv_bfloat16 h0,l0,h1,l1;
                split2(v0,h0,l0); split2(v1,h1,l1);
                size_t idx = qb + (size_t)rr*DMODEL + e0;
                *(uint32_t*)&AttH[idx] = pack2(h0,h1);
                *(uint32_t*)&AttL[idx] = pack2(l0,l1);
            }
        }
}

// ---------------- LayerNorm over D=1024 ------------------------------------
__global__ __launch_bounds__(256) void ln_k(
    const float* __restrict__ Y, const float* __restrict__ gamma,
    const float* __restrict__ beta, float* __restrict__ out)
{
    int row = blockIdx.x;
    int tid = threadIdx.x;
    float4 v = *(const float4*)&Y[(size_t)row*DMODEL + tid*4];
    float s  = v.x + v.y + v.z + v.w;
    float sq = v.x*v.x + v.y*v.y + v.z*v.z + v.w*v.w;
    #pragma unroll
    for (int o = 16; o > 0; o >>= 1) {
        s  += __shfl_xor_sync(0xFFFFFFFFu, s,  o);
        sq += __shfl_xor_sync(0xFFFFFFFFu, sq, o);
    }
    __shared__ float ss[8], ssq[8];
    int w = tid >> 5, l = tid & 31;
    if (l == 0) { ss[w] = s; ssq[w] = sq; }
    __syncthreads();
    if (tid == 0) {
        float S = 0.f, SQ = 0.f;
        #pragma unroll
        for (int i = 0; i < 8; i++) { S += ss[i]; SQ += ssq[i]; }
        ss[0] = S; ssq[0] = SQ;
    }
    __syncthreads();
    float mu  = ss[0] * (1.f/1024.f);
    float var = ssq[0] * (1.f/1024.f) - mu*mu;
    float inv = rsqrtf(var + 1e-3f);
    float4 gm = *(const float4*)&gamma[tid*4];
    float4 be = *(const float4*)&beta[tid*4];
    float4 o;
    o.x = (v.x - mu)*inv*gm.x + be.x;
    o.y = (v.y - mu)*inv*gm.y + be.y;
    o.z = (v.z - mu)*inv*gm.z + be.z;
    o.w = (v.w - mu)*inv*gm.w + be.w;
    *(float4*)&out[(size_t)row*DMODEL + tid*4] = o;
}

// ---------------- host entry ------------------------------------------------
extern "C" void kernel_launch(void* const* d_in, const int* in_sizes, int n_in,
                              void* d_out, int out_size)
{
    const float* x     = (const float*)d_in[0];
    const float* Wq    = (const float*)d_in[1];
    const float* bq    = (const float*)d_in[2];
    const float* Wk    = (const float*)d_in[3];
    const float* bk    = (const float*)d_in[4];
    const float* Wv    = (const float*)d_in[5];
    const float* bv    = (const float*)d_in[6];
    const float* Wo    = (const float*)d_in[7];
    const float* bo    = (const float*)d_in[8];
    const float* gamma = (const float*)d_in[9];
    const float* beta  = (const float*)d_in[10];
    float* out = (float*)d_out;

    float *Y, *KV, *Ksum;
    __nv_bfloat16 *Ah, *Al, *Qh, *Ql, *Kh, *Kl, *Vh, *Vl, *WTh, *WTl;
    cudaGetSymbolAddress((void**)&Y,    g_Y);
    cudaGetSymbolAddress((void**)&Ah,   g_Ah);
    cudaGetSymbolAddress((void**)&Al,   g_Al);
    cudaGetSymbolAddress((void**)&Qh,   g_Qh);
    cudaGetSymbolAddress((void**)&Ql,   g_Ql);
    cudaGetSymbolAddress((void**)&Kh,   g_Kh);
    cudaGetSymbolAddress((void**)&Kl,   g_Kl);
    cudaGetSymbolAddress((void**)&Vh,   g_Vh);
    cudaGetSymbolAddress((void**)&Vl,   g_Vl);
    cudaGetSymbolAddress((void**)&WTh,  g_WTh);
    cudaGetSymbolAddress((void**)&WTl,  g_WTl);
    cudaGetSymbolAddress((void**)&KV,   g_KV);
    cudaGetSymbolAddress((void**)&Ksum, g_Ksum);

    cudaFuncSetAttribute(gemm_qkv, cudaFuncAttributeMaxDynamicSharedMemorySize, GSMEM);
    cudaFuncSetAttribute(gemm_out, cudaFuncAttributeMaxDynamicSharedMemorySize, GSMEM);
    cudaFuncSetAttribute(qattn_t,  cudaFuncAttributeMaxDynamicSharedMemorySize, QSM);

    const size_t WSZ = (size_t)DMODEL*DMODEL;
    dim3 gqkv(DMODEL/BN, MTOT/BM, 3);   // (8, 128, 3)
    dim3 gout(DMODEL/BN, MTOT/BM);      // (8, 128)

    prep_k<<<7168, 256>>>(x, Wq, Wk, Wv, Wo, Ah, Al, WTh, WTl, KV, Ksum);

    gemm_qkv<<<gqkv, 256, GSMEM>>>(Ah, Al, WTh, WTl, bq, bk, bv,
                                   Qh, Ql, Kh, Kl, Vh, Vl);

    kv_ksum_t<<<dim3(NCHUNK, BH), 128>>>(Kh, Kl, Vh, Vl, KV, Ksum);
    qattn_t<<<dim3(SEQ/128, BH), 256, QSM>>>(Qh, Ql, KV, Ksum, Ah, Al);

    gemm_out<<<gout, 256, GSMEM>>>(Ah, Al, WTh + 3*WSZ, WTl + 3*WSZ, bo, x, Y);

    ln_k<<<MTOT, 256>>>(Y, gamma, beta, out);
}